// round 1
// baseline (speedup 1.0000x reference)
#include <cuda_runtime.h>

#define NB    4
#define NS    64
#define NC    8
#define NR    64
#define NPIX  65536
#define NSAMP 12
#define HID   64
#define COUT  8

typedef unsigned long long u64;

// Precomputed layer-1 table: A[b][sub][idx][h] = b1[h] + W1[h][0]*rc[idx] + sum_c W1[h][3+c]*ref[b][sub][c][idx]
__device__ __align__(16) float g_A[NB * NS * NR * HID];

// ---------- helpers ----------

__device__ __forceinline__ float geluf(float x) {
    // jax.nn.gelu approximate=True: 0.5*x*(1+tanh(0.7978845608*(x+0.044715*x^3)))
    float x2 = x * x;
    float t  = 0.7978845608028654f * x * fmaf(0.044715f, x2, 1.0f);
    float e  = __expf(2.0f * t);
    float th = 1.0f - __fdividef(2.0f, e + 1.0f);
    return 0.5f * x * (1.0f + th);
}

__device__ __forceinline__ u64 pack2(float lo, float hi) {
    u64 p;
    asm("mov.b64 %0, {%1, %2};" : "=l"(p) : "f"(lo), "f"(hi));
    return p;
}
__device__ __forceinline__ void unpack2(u64 p, float& lo, float& hi) {
    asm("mov.b64 {%0, %1}, %2;" : "=f"(lo), "=f"(hi) : "l"(p));
}
__device__ __forceinline__ void fma2(u64& acc, u64 a, u64 b) {
    // packed fp32x2 FMA (sm_100+), 2x fp32 throughput vs scalar FFMA
    asm("fma.rn.f32x2 %0, %1, %2, %0;" : "+l"(acc) : "l"(a), "l"(b));
}

// ---------- kernel 1: build A table (trivial cost) ----------

__global__ void precompute_A(const float* __restrict__ ref,
                             const float* __restrict__ W1,
                             const float* __restrict__ b1) {
    __shared__ float sref[NC][NR];
    __shared__ float sW1[HID][11];
    int bs = blockIdx.x;                       // b*64 + sub, 0..255
    const float* rp = ref + (size_t)bs * NC * NR;
    for (int i = threadIdx.x; i < NC * NR; i += 256)
        sref[i >> 6][i & 63] = rp[i];
    for (int i = threadIdx.x; i < HID * 11; i += 256)
        sW1[i / 11][i % 11] = W1[i];
    __syncthreads();

    int h  = threadIdx.x & 63;
    int rq = threadIdx.x >> 6;                 // 4 groups, 16 r each
    float w0 = sW1[h][0];
    float wc0 = sW1[h][3], wc1 = sW1[h][4], wc2 = sW1[h][5], wc3 = sW1[h][6];
    float wc4 = sW1[h][7], wc5 = sW1[h][8], wc6 = sW1[h][9], wc7 = sW1[h][10];
    float bb = b1[h];

    for (int r = rq * 16; r < rq * 16 + 16; r++) {
        float rc  = fmaf((float)r, 2.0f / 63.0f, -1.0f);  // linspace(-1,1,64)
        float acc = fmaf(w0, rc, bb);
        acc = fmaf(wc0, sref[0][r], acc);
        acc = fmaf(wc1, sref[1][r], acc);
        acc = fmaf(wc2, sref[2][r], acc);
        acc = fmaf(wc3, sref[3][r], acc);
        acc = fmaf(wc4, sref[4][r], acc);
        acc = fmaf(wc5, sref[5][r], acc);
        acc = fmaf(wc6, sref[6][r], acc);
        acc = fmaf(wc7, sref[7][r], acc);
        g_A[((size_t)bs * NR + r) * HID + h] = acc;
    }
}

// ---------- kernel 2: fused MLP ----------

__global__ void __launch_bounds__(256, 2) mlp_kernel(
    const float* __restrict__ pc,
    const int*   __restrict__ lookup,
    const int*   __restrict__ samp,
    const float* __restrict__ W1,
    const float* __restrict__ W2,
    const float* __restrict__ b2,
    const float* __restrict__ W3,
    const float* __restrict__ b3,
    float*       __restrict__ out)
{
    __shared__ __align__(16) float sW2[HID * HID];   // 16 KB, row j contiguous
    __shared__ __align__(16) float sW11[HID];        // W1[:,1]
    __shared__ __align__(16) float sW12[HID];        // W1[:,2]
    __shared__ float sb2[HID];
    __shared__ __align__(16) float sW3f[HID * COUT]; // [j][c] = W3[c][j]
    __shared__ int sidx[NSAMP][256];

    int tid = threadIdx.x;
    for (int i = tid; i < HID * HID; i += 256) sW2[i] = W2[i];
    if (tid < HID) {
        sW11[tid] = W1[tid * 11 + 1];
        sW12[tid] = W1[tid * 11 + 2];
        sb2[tid]  = b2[tid];
    }
    for (int i = tid; i < HID * COUT; i += 256) {
        int j = i >> 3, c = i & 7;
        sW3f[i] = W3[c * HID + j];
    }

    int gid = blockIdx.x * 256 + tid;     // 0 .. 262143
    int n   = gid & (NPIX - 1);
    int b   = gid >> 16;

    // 12 sample indices -> smem (avoids local-mem dynamic indexing)
    const int4* sp = reinterpret_cast<const int4*>(samp) + n * 3;
    int4 q0 = sp[0], q1 = sp[1], q2 = sp[2];
    sidx[0][tid] = q0.x;  sidx[1][tid]  = q0.y;  sidx[2][tid]  = q0.z;  sidx[3][tid]  = q0.w;
    sidx[4][tid] = q1.x;  sidx[5][tid]  = q1.y;  sidx[6][tid]  = q1.z;  sidx[7][tid]  = q1.w;
    sidx[8][tid] = q2.x;  sidx[9][tid]  = q2.y;  sidx[10][tid] = q2.z;  sidx[11][tid] = q2.w;

    int   sub = lookup[n];
    float px  = pc[n];
    float py  = pc[NPIX + n];
    __syncthreads();

    const float4* Abase = reinterpret_cast<const float4*>(g_A)
                          + (size_t)(b * NS + sub) * (NR * HID / 4);
    const float4* w11v = reinterpret_cast<const float4*>(sW11);
    const float4* w12v = reinterpret_cast<const float4*>(sW12);

    u64 outp0 = 0, outp1 = 0, outp2 = 0, outp3 = 0;  // (c0,c1) (c2,c3) (c4,c5) (c6,c7)

    for (int s = 0; s < NSAMP; s++) {
        int idx = sidx[s][tid];
        const float4* Arow = Abase + idx * (HID / 4);

        // layer 1: gather + coord term + gelu, pack K-pairs
        u64 h1p[HID / 2];
        #pragma unroll
        for (int k4 = 0; k4 < 16; k4++) {
            float4 a  = Arow[k4];
            float4 wa = w11v[k4];
            float4 wb = w12v[k4];
            float g0 = geluf(fmaf(wa.x, px, fmaf(wb.x, py, a.x)));
            float g1 = geluf(fmaf(wa.y, px, fmaf(wb.y, py, a.y)));
            float g2 = geluf(fmaf(wa.z, px, fmaf(wb.z, py, a.z)));
            float g3 = geluf(fmaf(wa.w, px, fmaf(wb.w, py, a.w)));
            h1p[2 * k4]     = pack2(g0, g1);
            h1p[2 * k4 + 1] = pack2(g2, g3);
        }

        // layer 2 (64x64 dot via f32x2 over K) + fused layer 3 + mean accumulation
        for (int j = 0; j < HID; j += 2) {
            const ulonglong2* r0 = reinterpret_cast<const ulonglong2*>(&sW2[(j + 0) * HID]);
            const ulonglong2* r1 = reinterpret_cast<const ulonglong2*>(&sW2[(j + 1) * HID]);
            u64 a00 = 0, a01 = 0, a10 = 0, a11 = 0;   // 4 chains for ILP
            #pragma unroll
            for (int k4 = 0; k4 < 16; k4 += 2) {
                ulonglong2 wa = r0[k4];
                ulonglong2 wb = r0[k4 + 1];
                ulonglong2 wc = r1[k4];
                ulonglong2 wd = r1[k4 + 1];
                fma2(a00, wa.x, h1p[2 * k4 + 0]);
                fma2(a00, wa.y, h1p[2 * k4 + 1]);
                fma2(a01, wb.x, h1p[2 * k4 + 2]);
                fma2(a01, wb.y, h1p[2 * k4 + 3]);
                fma2(a10, wc.x, h1p[2 * k4 + 0]);
                fma2(a10, wc.y, h1p[2 * k4 + 1]);
                fma2(a11, wd.x, h1p[2 * k4 + 2]);
                fma2(a11, wd.y, h1p[2 * k4 + 3]);
            }
            float l0, h0, l1, h1v;
            unpack2(a00, l0, h0);  unpack2(a01, l1, h1v);
            float h2a = geluf((l0 + h0) + (l1 + h1v) + sb2[j]);
            float l2, h2v, l3, h3v;
            unpack2(a10, l2, h2v); unpack2(a11, l3, h3v);
            float h2b = geluf((l2 + h2v) + (l3 + h3v) + sb2[j + 1]);

            u64 pa = pack2(h2a, h2a);
            u64 pb = pack2(h2b, h2b);
            const ulonglong2* w3a = reinterpret_cast<const ulonglong2*>(&sW3f[(j + 0) * COUT]);
            const ulonglong2* w3b = reinterpret_cast<const ulonglong2*>(&sW3f[(j + 1) * COUT]);
            ulonglong2 wa3 = w3a[0];
            ulonglong2 wb3 = w3b[0];
            fma2(outp0, wa3.x, pa);  fma2(outp1, wa3.y, pa);
            fma2(outp0, wb3.x, pb);  fma2(outp1, wb3.y, pb);
            ulonglong2 wa4 = w3a[1];
            ulonglong2 wb4 = w3b[1];
            fma2(outp2, wa4.x, pa);  fma2(outp3, wa4.y, pa);
            fma2(outp2, wb4.x, pb);  fma2(outp3, wb4.y, pb);
        }
    }

    const float inv = 1.0f / 12.0f;
    size_t base = (size_t)b * COUT * NPIX + n;
    float o0, o1;
    unpack2(outp0, o0, o1);
    out[base + 0 * (size_t)NPIX] = fmaf(o0, inv, __ldg(b3 + 0));
    out[base + 1 * (size_t)NPIX] = fmaf(o1, inv, __ldg(b3 + 1));
    unpack2(outp1, o0, o1);
    out[base + 2 * (size_t)NPIX] = fmaf(o0, inv, __ldg(b3 + 2));
    out[base + 3 * (size_t)NPIX] = fmaf(o1, inv, __ldg(b3 + 3));
    unpack2(outp2, o0, o1);
    out[base + 4 * (size_t)NPIX] = fmaf(o0, inv, __ldg(b3 + 4));
    out[base + 5 * (size_t)NPIX] = fmaf(o1, inv, __ldg(b3 + 5));
    unpack2(outp3, o0, o1);
    out[base + 6 * (size_t)NPIX] = fmaf(o0, inv, __ldg(b3 + 6));
    out[base + 7 * (size_t)NPIX] = fmaf(o1, inv, __ldg(b3 + 7));
}

// ---------- launch ----------

extern "C" void kernel_launch(void* const* d_in, const int* in_sizes, int n_in,
                              void* d_out, int out_size) {
    const float* ref    = (const float*)d_in[0];
    const float* pc     = (const float*)d_in[1];
    const int*   lookup = (const int*)d_in[2];
    const int*   samp   = (const int*)d_in[3];
    const float* W1     = (const float*)d_in[4];
    const float* b1     = (const float*)d_in[5];
    const float* W2     = (const float*)d_in[6];
    const float* b2     = (const float*)d_in[7];
    const float* W3     = (const float*)d_in[8];
    const float* b3     = (const float*)d_in[9];
    float* out = (float*)d_out;

    precompute_A<<<NB * NS, 256>>>(ref, W1, b1);
    mlp_kernel<<<(NB * NPIX) / 256, 256>>>(pc, lookup, samp, W1, W2, b2, W3, b3, out);
}

// round 3
// speedup vs baseline: 1.2769x; 1.2769x over previous
#include <cuda_runtime.h>
#include <cstdint>

#define NB    4
#define NS    64
#define NC    8
#define NR    64
#define NPIX  65536
#define NSAMP 12
#define HID   64
#define COUT  8

typedef unsigned long long u64;

// ---------------- dynamic smem layout ----------------
#define OFF_H1    0        // u64[32][128]  = 32768   (h1 packed k-pairs)  [reused as h2m f32[128][68] at end]
#define OFF_W2P   32768    // u64[32][64]   = 16384   (W2 packed k-pairs)
#define OFF_SIDX  49152    // int[12][128]  = 6144
#define OFF_SPX   55296    // f32[128]
#define OFF_SPY   55808
#define OFF_SAB   56320    // int[128]
#define OFF_W11   56832    // f32[64]
#define OFF_W12   57088
#define OFF_B2    57344
#define OFF_W3    57600    // f32[8][64] = 2048
#define OFF_PART  59648    // f32[128][8] = 4096
#define SMEM_TOTAL 63744

__device__ __align__(16) float g_A[NB * NS * NR * HID];

// ---------------- helpers ----------------
__device__ __forceinline__ float geluf(float x) {
    // 0.5*x*(1+tanh(0.79788456*(x+0.044715*x^3))), tanh via MUFU approx (err ~2^-10.4)
    float t = 0.7978845608028654f * x * fmaf(0.044715f, x * x, 1.0f);
    float th;
    asm("tanh.approx.f32 %0, %1;" : "=f"(th) : "f"(t));
    return 0.5f * x * (1.0f + th);
}
__device__ __forceinline__ u64 pack2(float lo, float hi) {
    u64 p;
    asm("mov.b64 %0, {%1, %2};" : "=l"(p) : "f"(lo), "f"(hi));
    return p;
}
__device__ __forceinline__ void unpack2(u64 p, float& lo, float& hi) {
    asm("mov.b64 {%0, %1}, %2;" : "=f"(lo), "=f"(hi) : "l"(p));
}
__device__ __forceinline__ void fma2(u64& acc, u64 a, u64 b) {
    asm("fma.rn.f32x2 %0, %1, %2, %0;" : "+l"(acc) : "l"(a), "l"(b));
}

// ---------------- kernel 1: layer-1 constant table ----------------
__global__ void precompute_A(const float* __restrict__ ref,
                             const float* __restrict__ W1,
                             const float* __restrict__ b1) {
    __shared__ float sref[NC][NR];
    __shared__ float sW1[HID][11];
    int bs = blockIdx.x;
    const float* rp = ref + (size_t)bs * NC * NR;
    for (int i = threadIdx.x; i < NC * NR; i += 256) sref[i >> 6][i & 63] = rp[i];
    for (int i = threadIdx.x; i < HID * 11; i += 256) sW1[i / 11][i % 11] = W1[i];
    __syncthreads();
    int h = threadIdx.x & 63, rq = threadIdx.x >> 6;
    float w0 = sW1[h][0], bb = b1[h];
    float wc[8];
    #pragma unroll
    for (int c = 0; c < 8; c++) wc[c] = sW1[h][3 + c];
    for (int r = rq * 16; r < rq * 16 + 16; r++) {
        float rc  = fmaf((float)r, 2.0f / 63.0f, -1.0f);
        float acc = fmaf(w0, rc, bb);
        #pragma unroll
        for (int c = 0; c < 8; c++) acc = fmaf(wc[c], sref[c][r], acc);
        g_A[((size_t)bs * NR + r) * HID + h] = acc;
    }
}

// ---------------- kernel 2: register-blocked fused MLP ----------------
__global__ void __launch_bounds__(256) mlp_kernel(
    const float* __restrict__ pc,
    const int*   __restrict__ lookup,
    const int*   __restrict__ samp,
    const float* __restrict__ W1,
    const float* __restrict__ W2,
    const float* __restrict__ b2,
    const float* __restrict__ W3,
    const float* __restrict__ b3,
    float*       __restrict__ out)
{
    extern __shared__ __align__(16) char smem[];
    const int tid  = threadIdx.x;
    const int r    = tid & 127;        // build-phase point id / final-phase pixel id
    const int half = tid >> 7;         // build/final-phase column half
    const int pg   = tid >> 4;         // GEMM: point group  (8 points)
    const int jg   = tid & 15;         // GEMM: j group      (4 outputs)
    const int p0   = pg * 8;
    const int j0   = jg * 4;

    const int tileb = blockIdx.x;      // 0..2047
    const int b     = tileb >> 9;
    const int n0    = (tileb & 511) * 128;

    u64*   h1p  = (u64*)  (smem + OFF_H1);     // [k2][128]
    u64*   W2p  = (u64*)  (smem + OFF_W2P);    // [k2][64]
    int*   sidx = (int*)  (smem + OFF_SIDX);   // [12][128]
    float* spx  = (float*)(smem + OFF_SPX);
    float* spy  = (float*)(smem + OFF_SPY);
    int*   sab  = (int*)  (smem + OFF_SAB);
    float* sW11 = (float*)(smem + OFF_W11);
    float* sW12 = (float*)(smem + OFF_W12);
    float* sb2  = (float*)(smem + OFF_B2);
    float* sW3  = (float*)(smem + OFF_W3);
    float* part = (float*)(smem + OFF_PART);

    // ---- prologue loads ----
    if (tid < 128) {
        spx[tid] = pc[n0 + tid];
        spy[tid] = pc[NPIX + n0 + tid];
        int sub  = lookup[n0 + tid];
        sab[tid] = ((b << 6) + sub) << 12;       // float index into g_A
    }
    for (int i = tid; i < 128 * NSAMP; i += 256) {
        int rr = i / NSAMP, ss = i % NSAMP;
        sidx[ss * 128 + rr] = samp[(size_t)(n0 + rr) * NSAMP + ss];
    }
    // W2 packed k-pairs: W2p[k2*64 + j] = (W2[j][2k2], W2[j][2k2+1])
    for (int i = tid; i < HID * HID / 2; i += 256) {
        int k2 = i >> 6, j = i & 63;
        W2p[k2 * 64 + j] = *(const u64*)(W2 + j * HID + 2 * k2);
    }
    if (tid < HID) {
        sW11[tid] = W1[tid * 11 + 1];
        sW12[tid] = W1[tid * 11 + 2];
        sb2[tid]  = b2[tid];
    }
    for (int i = tid; i < COUT * HID; i += 256) sW3[i] = W3[i];

    const float4* w1a = (const float4*)(sW11 + half * 32);
    const float4* w1b = (const float4*)(sW12 + half * 32);

    float h2acc[32];
    #pragma unroll
    for (int i = 0; i < 32; i++) h2acc[i] = 0.0f;

    float bj0, bj1, bj2, bj3;

    for (int s = 0; s < NSAMP; s++) {
        __syncthreads();   // prologue done (s=0) / previous GEMM reads done

        // ---- build h1 tile for sample s (thread: point r, k-half 'half') ----
        {
            int idx = sidx[s * 128 + r];
            const float4* Ap = (const float4*)(g_A + sab[r] + idx * 64 + half * 32);
            float px = spx[r], py = spy[r];
            #pragma unroll
            for (int q = 0; q < 8; q++) {
                float4 a  = Ap[q];
                float4 wa = w1a[q];
                float4 wb = w1b[q];
                float g0 = geluf(fmaf(wa.x, px, fmaf(wb.x, py, a.x)));
                float g1 = geluf(fmaf(wa.y, px, fmaf(wb.y, py, a.y)));
                float g2 = geluf(fmaf(wa.z, px, fmaf(wb.z, py, a.z)));
                float g3 = geluf(fmaf(wa.w, px, fmaf(wb.w, py, a.w)));
                int k2 = half * 16 + q * 2;
                h1p[(k2 + 0) * 128 + r] = pack2(g0, g1);
                h1p[(k2 + 1) * 128 + r] = pack2(g2, g3);
            }
        }
        if (s == 0) {
            bj0 = sb2[j0 + 0]; bj1 = sb2[j0 + 1]; bj2 = sb2[j0 + 2]; bj3 = sb2[j0 + 3];
        }
        __syncthreads();

        // ---- GEMM: C[8p x 4j] += h1[8p x 64k] * W2^T[64k x 4j], fp32x2 over k ----
        u64 acc[32];
        #pragma unroll
        for (int i = 0; i < 32; i++) acc[i] = 0;

        #pragma unroll 4
        for (int k2 = 0; k2 < 32; k2++) {
            const ulonglong2* wrow = (const ulonglong2*)(W2p + k2 * 64 + j0);
            const ulonglong2* arow = (const ulonglong2*)(h1p + k2 * 128 + p0);
            ulonglong2 w01 = wrow[0];
            ulonglong2 w23 = wrow[1];
            #pragma unroll
            for (int ph = 0; ph < 4; ph++) {
                ulonglong2 ap = arow[ph];
                fma2(acc[(2 * ph + 0) * 4 + 0], ap.x, w01.x);
                fma2(acc[(2 * ph + 0) * 4 + 1], ap.x, w01.y);
                fma2(acc[(2 * ph + 0) * 4 + 2], ap.x, w23.x);
                fma2(acc[(2 * ph + 0) * 4 + 3], ap.x, w23.y);
                fma2(acc[(2 * ph + 1) * 4 + 0], ap.y, w01.x);
                fma2(acc[(2 * ph + 1) * 4 + 1], ap.y, w01.y);
                fma2(acc[(2 * ph + 1) * 4 + 2], ap.y, w23.x);
                fma2(acc[(2 * ph + 1) * 4 + 3], ap.y, w23.y);
            }
        }

        // ---- epilogue: bias + gelu + accumulate over samples ----
        #pragma unroll
        for (int p = 0; p < 8; p++) {
            float lo, hi;
            unpack2(acc[p * 4 + 0], lo, hi);
            h2acc[p * 4 + 0] += geluf(lo + hi + bj0);
            unpack2(acc[p * 4 + 1], lo, hi);
            h2acc[p * 4 + 1] += geluf(lo + hi + bj1);
            unpack2(acc[p * 4 + 2], lo, hi);
            h2acc[p * 4 + 2] += geluf(lo + hi + bj2);
            unpack2(acc[p * 4 + 3], lo, hi);
            h2acc[p * 4 + 3] += geluf(lo + hi + bj3);
        }
    }
    __syncthreads();   // all GEMM reads of h1p complete -> safe to reuse buffer

    // ---- h2 mean -> smem (reuse OFF_H1 region, pitch 68 to avoid bank camping) ----
    float* h2m = (float*)(smem + OFF_H1);      // [128][68]
    const float inv = 1.0f / 12.0f;
    #pragma unroll
    for (int p = 0; p < 8; p++) {
        float4 v = make_float4(h2acc[p * 4 + 0] * inv, h2acc[p * 4 + 1] * inv,
                               h2acc[p * 4 + 2] * inv, h2acc[p * 4 + 3] * inv);
        *(float4*)(h2m + (p0 + p) * 68 + j0) = v;
    }
    __syncthreads();

    // ---- layer 3 (mean folded): thread (r, half) covers j in [half*32, half*32+32) ----
    {
        float pacc[COUT];
        #pragma unroll
        for (int c = 0; c < COUT; c++) pacc[c] = 0.0f;
        const float* hrow = h2m + r * 68 + half * 32;
        #pragma unroll
        for (int q = 0; q < 8; q++) {
            float4 h4 = *(const float4*)(hrow + q * 4);
            int j = half * 32 + q * 4;
            #pragma unroll
            for (int c = 0; c < COUT; c++) {
                const float* w3r = sW3 + c * HID + j;
                pacc[c] = fmaf(w3r[0], h4.x, pacc[c]);
                pacc[c] = fmaf(w3r[1], h4.y, pacc[c]);
                pacc[c] = fmaf(w3r[2], h4.z, pacc[c]);
                pacc[c] = fmaf(w3r[3], h4.w, pacc[c]);
            }
        }
        if (half == 1) {
            #pragma unroll
            for (int c = 0; c < COUT; c++) part[r * COUT + c] = pacc[c];
        }
        __syncthreads();
        if (half == 0) {
            size_t base = (size_t)b * COUT * NPIX + n0 + r;
            #pragma unroll
            for (int c = 0; c < COUT; c++)
                out[base + (size_t)c * NPIX] = pacc[c] + part[r * COUT + c] + __ldg(b3 + c);
        }
    }
}

// ---------------- launch ----------------
extern "C" void kernel_launch(void* const* d_in, const int* in_sizes, int n_in,
                              void* d_out, int out_size) {
    const float* ref    = (const float*)d_in[0];
    const float* pc     = (const float*)d_in[1];
    const int*   lookup = (const int*)d_in[2];
    const int*   samp   = (const int*)d_in[3];
    const float* W1     = (const float*)d_in[4];
    const float* b1     = (const float*)d_in[5];
    const float* W2     = (const float*)d_in[6];
    const float* b2     = (const float*)d_in[7];
    const float* W3     = (const float*)d_in[8];
    const float* b3     = (const float*)d_in[9];
    float* out = (float*)d_out;

    cudaFuncSetAttribute(mlp_kernel, cudaFuncAttributeMaxDynamicSharedMemorySize, SMEM_TOTAL);

    precompute_A<<<NB * NS, 256>>>(ref, W1, b1);
    mlp_kernel<<<NB * (NPIX / 128), 256, SMEM_TOTAL>>>(
        pc, lookup, samp, W1, W2, b2, W3, b3, out);
}

// round 5
// speedup vs baseline: 2.7404x; 2.1461x over previous
#include <cuda_runtime.h>
#include <cuda_bf16.h>
#include <cstdint>

#define NB    4
#define NS    64
#define NC    8
#define NR    64
#define NPIX  65536
#define NSAMP 12
#define HID   64
#define COUT  8

// ---------------- dynamic smem layout ----------------
// A tiles (h1): 128 rows x 64 bf16, pitch 144B (conflict-free ldmatrix)
#define OFF_AHI   0            // 128*144 = 18432
#define OFF_ALO   18432        // 18432          (AHI+ALO reused as h2m f32[128][72] = 36864)
#define OFF_WHI   36864        // 64*144 = 9216
#define OFF_WLO   46080        // 9216
#define OFF_SIDX  55296        // int[12][128] = 6144
#define OFF_SPX   61440        // f32[128]
#define OFF_SPY   61952
#define OFF_SAB   62464        // int[128]
#define OFF_W11   62976        // f32[64]
#define OFF_W12   63232
#define OFF_B2    63488
#define OFF_W3    63744        // f32[8][64] = 2048
#define OFF_PART  65792        // f32[128][8] = 4096
#define SMEM_TOTAL 69888

__device__ __align__(16) float g_A[NB * NS * NR * HID];

// ---------------- helpers ----------------
__device__ __forceinline__ uint32_t smem_u32(const void* p) {
    uint32_t a;
    asm("{ .reg .u64 t; cvta.to.shared.u64 t, %1; cvt.u32.u64 %0, t; }" : "=r"(a) : "l"(p));
    return a;
}
__device__ __forceinline__ float geluf(float x) {
    float t = 0.7978845608028654f * x * fmaf(0.044715f, x * x, 1.0f);
    float th;
    asm("tanh.approx.f32 %0, %1;" : "=f"(th) : "f"(t));
    return 0.5f * x * (1.0f + th);
}
__device__ __forceinline__ void ldmx4(uint32_t* r, uint32_t addr) {
    asm volatile("ldmatrix.sync.aligned.m8n8.x4.shared.b16 {%0,%1,%2,%3}, [%4];"
        : "=r"(r[0]), "=r"(r[1]), "=r"(r[2]), "=r"(r[3]) : "r"(addr));
}
__device__ __forceinline__ void mma16816(float* c, const uint32_t* a, uint32_t b0, uint32_t b1) {
    asm volatile("mma.sync.aligned.m16n8k16.row.col.f32.bf16.bf16.f32 "
        "{%0,%1,%2,%3}, {%4,%5,%6,%7}, {%8,%9}, {%0,%1,%2,%3};"
        : "+f"(c[0]), "+f"(c[1]), "+f"(c[2]), "+f"(c[3])
        : "r"(a[0]), "r"(a[1]), "r"(a[2]), "r"(a[3]), "r"(b0), "r"(b1));
}

// ---------------- kernel 1: layer-1 constant table ----------------
__global__ void precompute_A(const float* __restrict__ ref,
                             const float* __restrict__ W1,
                             const float* __restrict__ b1) {
    __shared__ float sref[NC][NR];
    __shared__ float sW1[HID][11];
    int bs = blockIdx.x;
    const float* rp = ref + (size_t)bs * NC * NR;
    for (int i = threadIdx.x; i < NC * NR; i += 256) sref[i >> 6][i & 63] = rp[i];
    for (int i = threadIdx.x; i < HID * 11; i += 256) sW1[i / 11][i % 11] = W1[i];
    __syncthreads();
    int h = threadIdx.x & 63, rq = threadIdx.x >> 6;
    float w0 = sW1[h][0], bb = b1[h];
    float wc[8];
    #pragma unroll
    for (int c = 0; c < 8; c++) wc[c] = sW1[h][3 + c];
    for (int r = rq * 16; r < rq * 16 + 16; r++) {
        float rc  = fmaf((float)r, 2.0f / 63.0f, -1.0f);
        float acc = fmaf(w0, rc, bb);
        #pragma unroll
        for (int c = 0; c < 8; c++) acc = fmaf(wc[c], sref[c][r], acc);
        g_A[((size_t)bs * NR + r) * HID + h] = acc;
    }
}

// ---------------- kernel 2: HMMA fused MLP ----------------
__global__ void __launch_bounds__(256, 2) mlp_mma_kernel(
    const float* __restrict__ pc,
    const int*   __restrict__ lookup,
    const int*   __restrict__ samp,
    const float* __restrict__ W1,
    const float* __restrict__ W2,
    const float* __restrict__ b2,
    const float* __restrict__ W3,
    const float* __restrict__ b3,
    float*       __restrict__ out)
{
    extern __shared__ __align__(16) char smem[];
    const uint32_t sbase = smem_u32(smem);
    const int tid  = threadIdx.x;
    const int lane = tid & 31;
    const int w    = tid >> 5;          // warp 0..7, owns point rows 16w..16w+15
    const int r    = tid & 127;         // build/final-phase point id
    const int half = tid >> 7;          // build/final-phase k-half

    const int tileb = blockIdx.x;       // 0..2047
    const int b     = tileb >> 9;
    const int n0    = (tileb & 511) * 128;

    int*   sidx = (int*)  (smem + OFF_SIDX);
    float* spx  = (float*)(smem + OFF_SPX);
    float* spy  = (float*)(smem + OFF_SPY);
    int*   sab  = (int*)  (smem + OFF_SAB);
    float* sW11 = (float*)(smem + OFF_W11);
    float* sW12 = (float*)(smem + OFF_W12);
    float* sb2  = (float*)(smem + OFF_B2);
    float* sW3  = (float*)(smem + OFF_W3);
    float* part = (float*)(smem + OFF_PART);

    // ---- prologue ----
    if (tid < 128) {
        spx[tid] = pc[n0 + tid];
        spy[tid] = pc[NPIX + n0 + tid];
        int sub  = lookup[n0 + tid];
        sab[tid] = ((b << 6) + sub) << 12;   // float index into g_A
    }
    for (int i = tid; i < 128 * NSAMP; i += 256) {
        int rr = i / NSAMP, ss = i % NSAMP;
        sidx[ss * 128 + rr] = samp[(size_t)(n0 + rr) * NSAMP + ss];
    }
    // W2 -> bf16 hi/lo tiles, [j][k] rows, pitch 144
    for (int i = tid; i < HID * HID; i += 256) {
        int j = i >> 6, k = i & 63;
        float wv = W2[i];
        __nv_bfloat16 hi = __float2bfloat16(wv);
        __nv_bfloat16 lo = __float2bfloat16(wv - __bfloat162float(hi));
        *(__nv_bfloat16*)(smem + OFF_WHI + j * 144 + 2 * k) = hi;
        *(__nv_bfloat16*)(smem + OFF_WLO + j * 144 + 2 * k) = lo;
    }
    if (tid < HID) {
        sW11[tid] = W1[tid * 11 + 1];
        sW12[tid] = W1[tid * 11 + 2];
        sb2[tid]  = b2[tid];
    }
    for (int i = tid; i < COUT * HID; i += 256) sW3[i] = W3[i];

    // ldmatrix lane addresses
    const uint32_t a_row  = (uint32_t)(w * 16 + (lane & 7) + ((lane >> 3) & 1) * 8);
    const uint32_t a_coff = (uint32_t)(((lane >> 4) & 1) * 16);
    const uint32_t aHi = sbase + OFF_AHI + a_row * 144 + a_coff;
    const uint32_t aLo = sbase + OFF_ALO + a_row * 144 + a_coff;
    const uint32_t b_row  = (uint32_t)((lane & 7) + ((lane >> 4) & 1) * 8);
    const uint32_t b_coff = (uint32_t)(((lane >> 3) & 1) * 16);
    const uint32_t bHi = sbase + OFF_WHI + b_row * 144 + b_coff;
    const uint32_t bLo = sbase + OFF_WLO + b_row * 144 + b_coff;

    const float4* w1a = (const float4*)(sW11 + half * 32);
    const float4* w1b = (const float4*)(sW12 + half * 32);

    float h2acc[32];
    #pragma unroll
    for (int i = 0; i < 32; i++) h2acc[i] = 0.0f;

    for (int s = 0; s < NSAMP; s++) {
        __syncthreads();   // prologue done / previous sample's ldmatrix reads done

        // ---- build h1 (fp32) -> bf16 hi/lo tiles; thread = (point r, k-half) ----
        {
            int idx = sidx[s * 128 + r];
            const float4* Ap = (const float4*)(g_A + sab[r] + idx * 64 + half * 32);
            float px = spx[r], py = spy[r];
            uint32_t hp[16], lp[16];
            #pragma unroll
            for (int q = 0; q < 8; q++) {
                float4 a  = Ap[q];
                float4 wa = w1a[q];
                float4 wb = w1b[q];
                float g0 = geluf(fmaf(wa.x, px, fmaf(wb.x, py, a.x)));
                float g1 = geluf(fmaf(wa.y, px, fmaf(wb.y, py, a.y)));
                float g2 = geluf(fmaf(wa.z, px, fmaf(wb.z, py, a.z)));
                float g3 = geluf(fmaf(wa.w, px, fmaf(wb.w, py, a.w)));
                __nv_bfloat16 h0 = __float2bfloat16(g0), h1v = __float2bfloat16(g1);
                __nv_bfloat16 h2 = __float2bfloat16(g2), h3v = __float2bfloat16(g3);
                __nv_bfloat16 l0 = __float2bfloat16(g0 - __bfloat162float(h0));
                __nv_bfloat16 l1 = __float2bfloat16(g1 - __bfloat162float(h1v));
                __nv_bfloat16 l2 = __float2bfloat16(g2 - __bfloat162float(h2));
                __nv_bfloat16 l3 = __float2bfloat16(g3 - __bfloat162float(h3v));
                hp[q*2+0] = (uint32_t)__bfloat16_as_ushort(h0) | ((uint32_t)__bfloat16_as_ushort(h1v) << 16);
                hp[q*2+1] = (uint32_t)__bfloat16_as_ushort(h2) | ((uint32_t)__bfloat16_as_ushort(h3v) << 16);
                lp[q*2+0] = (uint32_t)__bfloat16_as_ushort(l0) | ((uint32_t)__bfloat16_as_ushort(l1) << 16);
                lp[q*2+1] = (uint32_t)__bfloat16_as_ushort(l2) | ((uint32_t)__bfloat16_as_ushort(l3) << 16);
            }
            char* hrow = smem + OFF_AHI + r * 144 + half * 64;
            char* lrow = smem + OFF_ALO + r * 144 + half * 64;
            #pragma unroll
            for (int t = 0; t < 4; t++) {
                *(uint4*)(hrow + t * 16) = make_uint4(hp[4*t], hp[4*t+1], hp[4*t+2], hp[4*t+3]);
                *(uint4*)(lrow + t * 16) = make_uint4(lp[4*t], lp[4*t+1], lp[4*t+2], lp[4*t+3]);
            }
        }
        __syncthreads();

        // ---- HMMA: warp w computes rows 16w..16w+15 x all 64 cols ----
        #pragma unroll
        for (int nh = 0; nh < 2; nh++) {            // n-halves: cols 32nh..32nh+31
            float c[16];
            #pragma unroll
            for (int i = 0; i < 16; i++) c[i] = 0.0f;

            #pragma unroll
            for (int ks = 0; ks < 4; ks++) {        // k-steps of 16
                uint32_t ah[4], al[4];
                ldmx4(ah, aHi + ks * 32);
                ldmx4(al, aLo + ks * 32);
                #pragma unroll
                for (int tp = 0; tp < 2; tp++) {    // n-tile pairs of 16 cols
                    uint32_t bh[4], bl[4];
                    uint32_t boff = (uint32_t)((nh * 32 + tp * 16) * 144 + ks * 32);
                    ldmx4(bh, bHi + boff);
                    ldmx4(bl, bLo + boff);
                    float* c0 = c + (tp * 2 + 0) * 4;
                    float* c1 = c + (tp * 2 + 1) * 4;
                    mma16816(c0, ah, bh[0], bh[1]);
                    mma16816(c1, ah, bh[2], bh[3]);
                    mma16816(c0, al, bh[0], bh[1]);
                    mma16816(c1, al, bh[2], bh[3]);
                    mma16816(c0, ah, bl[0], bl[1]);
                    mma16816(c1, ah, bl[2], bl[3]);
                }
            }
            // epilogue: bias + gelu + accumulate over samples (register-only)
            int jq = (lane & 3) * 2;
            #pragma unroll
            for (int t4 = 0; t4 < 4; t4++) {
                int j = nh * 32 + t4 * 8 + jq;
                float bj0 = sb2[j], bj1 = sb2[j + 1];
                float* h2 = h2acc + (nh * 4 + t4) * 4;
                h2[0] += geluf(c[t4*4+0] + bj0);
                h2[1] += geluf(c[t4*4+1] + bj1);
                h2[2] += geluf(c[t4*4+2] + bj0);
                h2[3] += geluf(c[t4*4+3] + bj1);
            }
        }
    }
    __syncthreads();   // all ldmatrix reads of A done -> safe to reuse as h2m

    // ---- h2 mean -> smem [128][72] (reuses A region) ----
    float* h2m = (float*)(smem + OFF_AHI);
    {
        const float inv = 1.0f / 12.0f;
        int pa = w * 16 + (lane >> 2);
        int jq = (lane & 3) * 2;
        #pragma unroll
        for (int nt = 0; nt < 8; nt++) {
            int j = nt * 8 + jq;
            h2m[pa * 72 + j]           = h2acc[nt*4+0] * inv;
            h2m[pa * 72 + j + 1]       = h2acc[nt*4+1] * inv;
            h2m[(pa + 8) * 72 + j]     = h2acc[nt*4+2] * inv;
            h2m[(pa + 8) * 72 + j + 1] = h2acc[nt*4+3] * inv;
        }
    }
    __syncthreads();

    // ---- layer 3 (mean folded): thread (r, half) covers j in [32*half, 32*half+32) ----
    {
        float pacc[COUT];
        #pragma unroll
        for (int c = 0; c < COUT; c++) pacc[c] = 0.0f;
        const float* hrow = h2m + r * 72 + half * 32;
        #pragma unroll
        for (int q = 0; q < 8; q++) {
            float4 h4 = *(const float4*)(hrow + q * 4);
            int j = half * 32 + q * 4;
            #pragma unroll
            for (int c = 0; c < COUT; c++) {
                const float* w3r = sW3 + c * HID + j;
                pacc[c] = fmaf(w3r[0], h4.x, pacc[c]);
                pacc[c] = fmaf(w3r[1], h4.y, pacc[c]);
                pacc[c] = fmaf(w3r[2], h4.z, pacc[c]);
                pacc[c] = fmaf(w3r[3], h4.w, pacc[c]);
            }
        }
        if (half == 1) {
            #pragma unroll
            for (int c = 0; c < COUT; c++) part[r * COUT + c] = pacc[c];
        }
        __syncthreads();
        if (half == 0) {
            size_t base = (size_t)b * COUT * NPIX + n0 + r;
            #pragma unroll
            for (int c = 0; c < COUT; c++)
                out[base + (size_t)c * NPIX] = pacc[c] + part[r * COUT + c] + __ldg(b3 + c);
        }
    }
}

// ---------------- launch ----------------
extern "C" void kernel_launch(void* const* d_in, const int* in_sizes, int n_in,
                              void* d_out, int out_size) {
    const float* ref    = (const float*)d_in[0];
    const float* pc     = (const float*)d_in[1];
    const int*   lookup = (const int*)d_in[2];
    const int*   samp   = (const int*)d_in[3];
    const float* W1     = (const float*)d_in[4];
    const float* b1     = (const float*)d_in[5];
    const float* W2     = (const float*)d_in[6];
    const float* b2     = (const float*)d_in[7];
    const float* W3     = (const float*)d_in[8];
    const float* b3     = (const float*)d_in[9];
    float* out = (float*)d_out;

    cudaFuncSetAttribute(mlp_mma_kernel, cudaFuncAttributeMaxDynamicSharedMemorySize, SMEM_TOTAL);

    precompute_A<<<NB * NS, 256>>>(ref, W1, b1);
    mlp_mma_kernel<<<NB * (NPIX / 128), 256, SMEM_TOTAL>>>(
        pc, lookup, samp, W1, W2, b2, W3, b3, out);
}

// round 6
// speedup vs baseline: 4.2575x; 1.5536x over previous
#include <cuda_runtime.h>
#include <cuda_fp16.h>
#include <cstdint>

#define NB    4
#define NS    64
#define NC    8
#define NR    64
#define NPIX  65536
#define NSAMP 12
#define HID   64
#define COUT  8

// ---------------- dynamic smem layout ----------------
// A tiles (h1): 128 rows x 64 fp16, pitch 144B; double buffered.
#define OFF_A0    0            // 18432
#define OFF_A1    18432        // 18432   (A0+A1 = 36864 reused as h2m f32[128][72])
#define OFF_W     36864        // 64*144 = 9216
#define OFF_SIDX  46080        // int[12][128] = 6144
#define OFF_SPX   52224        // f32[128]
#define OFF_SPY   52736
#define OFF_SAB   53248        // int[128]
#define OFF_W11   53760        // f32[64]
#define OFF_W12   54016
#define OFF_B2    54272
#define OFF_W3    54528        // f32[8][64] = 2048
#define OFF_PART  56576        // f32[128][8] = 4096
#define SMEM_TOTAL 60672

__device__ __align__(16) float g_A[NB * NS * NR * HID];

// ---------------- helpers ----------------
__device__ __forceinline__ uint32_t smem_u32(const void* p) {
    uint32_t a;
    asm("{ .reg .u64 t; cvta.to.shared.u64 t, %1; cvt.u32.u64 %0, t; }" : "=r"(a) : "l"(p));
    return a;
}
__device__ __forceinline__ float geluf(float x) {
    float t = 0.7978845608028654f * x * fmaf(0.044715f, x * x, 1.0f);
    float th;
    asm("tanh.approx.f32 %0, %1;" : "=f"(th) : "f"(t));
    return 0.5f * x * (1.0f + th);
}
__device__ __forceinline__ uint32_t packh2(float a, float b) {
    uint32_t r;
    asm("cvt.rn.f16x2.f32 %0, %2, %1;" : "=r"(r) : "f"(a), "f"(b));
    return r;
}
__device__ __forceinline__ void ldmx4(uint32_t* r, uint32_t addr) {
    asm volatile("ldmatrix.sync.aligned.m8n8.x4.shared.b16 {%0,%1,%2,%3}, [%4];"
        : "=r"(r[0]), "=r"(r[1]), "=r"(r[2]), "=r"(r[3]) : "r"(addr));
}
__device__ __forceinline__ void mma16816(float* c, const uint32_t* a, uint32_t b0, uint32_t b1) {
    asm volatile("mma.sync.aligned.m16n8k16.row.col.f32.f16.f16.f32 "
        "{%0,%1,%2,%3}, {%4,%5,%6,%7}, {%8,%9}, {%0,%1,%2,%3};"
        : "+f"(c[0]), "+f"(c[1]), "+f"(c[2]), "+f"(c[3])
        : "r"(a[0]), "r"(a[1]), "r"(a[2]), "r"(a[3]), "r"(b0), "r"(b1));
}

// ---------------- kernel 1: layer-1 constant table ----------------
__global__ void precompute_A(const float* __restrict__ ref,
                             const float* __restrict__ W1,
                             const float* __restrict__ b1) {
    __shared__ float sref[NC][NR];
    __shared__ float sW1[HID][11];
    int bs = blockIdx.x;
    const float* rp = ref + (size_t)bs * NC * NR;
    for (int i = threadIdx.x; i < NC * NR; i += 256) sref[i >> 6][i & 63] = rp[i];
    for (int i = threadIdx.x; i < HID * 11; i += 256) sW1[i / 11][i % 11] = W1[i];
    __syncthreads();
    int h = threadIdx.x & 63, rq = threadIdx.x >> 6;
    float w0 = sW1[h][0], bb = b1[h];
    float wc[8];
    #pragma unroll
    for (int c = 0; c < 8; c++) wc[c] = sW1[h][3 + c];
    for (int r = rq * 16; r < rq * 16 + 16; r++) {
        float rc  = fmaf((float)r, 2.0f / 63.0f, -1.0f);
        float acc = fmaf(w0, rc, bb);
        #pragma unroll
        for (int c = 0; c < 8; c++) acc = fmaf(wc[c], sref[c][r], acc);
        g_A[((size_t)bs * NR + r) * HID + h] = acc;
    }
}

// ---------------- kernel 2: fp16 HMMA fused MLP, W-frags in registers ----------------
__global__ void __launch_bounds__(256, 2) mlp_mma_kernel(
    const float* __restrict__ pc,
    const int*   __restrict__ lookup,
    const int*   __restrict__ samp,
    const float* __restrict__ W1,
    const float* __restrict__ W2,
    const float* __restrict__ b2,
    const float* __restrict__ W3,
    const float* __restrict__ b3,
    float*       __restrict__ out)
{
    extern __shared__ __align__(16) char smem[];
    const uint32_t sbase = smem_u32(smem);
    const int tid  = threadIdx.x;
    const int lane = tid & 31;
    const int w    = tid >> 5;
    const int rg   = w & 3;             // row group: rows 32rg..32rg+31
    const int ch   = w >> 2;            // col half:  cols 32ch..32ch+31
    const int r    = tid & 127;         // build/final-phase point id
    const int half = tid >> 7;          // build/final-phase k-half

    const int tileb = blockIdx.x;       // 0..2047
    const int b     = tileb >> 9;
    const int n0    = (tileb & 511) * 128;

    int*   sidx = (int*)  (smem + OFF_SIDX);
    float* spx  = (float*)(smem + OFF_SPX);
    float* spy  = (float*)(smem + OFF_SPY);
    int*   sab  = (int*)  (smem + OFF_SAB);
    float* sW11 = (float*)(smem + OFF_W11);
    float* sW12 = (float*)(smem + OFF_W12);
    float* sb2  = (float*)(smem + OFF_B2);
    float* sW3  = (float*)(smem + OFF_W3);
    float* part = (float*)(smem + OFF_PART);

    // ---- prologue ----
    if (tid < 128) {
        spx[tid] = pc[n0 + tid];
        spy[tid] = pc[NPIX + n0 + tid];
        int sub  = lookup[n0 + tid];
        sab[tid] = ((b << 6) + sub) << 12;   // float index into g_A
    }
    for (int i = tid; i < 128 * NSAMP; i += 256) {
        int rr = i / NSAMP, ss = i % NSAMP;
        sidx[ss * 128 + rr] = samp[(size_t)(n0 + rr) * NSAMP + ss];
    }
    // W2 -> fp16 tile [j][k], pitch 144
    for (int i = tid; i < HID * HID; i += 256) {
        int j = i >> 6, k = i & 63;
        *(__half*)(smem + OFF_W + j * 144 + 2 * k) = __float2half_rn(W2[i]);
    }
    if (tid < HID) {
        sW11[tid] = W1[tid * 11 + 1];
        sW12[tid] = W1[tid * 11 + 2];
        sb2[tid]  = b2[tid];
    }
    for (int i = tid; i < COUT * HID; i += 256) sW3[i] = W3[i];
    __syncthreads();

    // ---- load W fragments once; resident for all samples ----
    // B-tile lane address pattern (j-row within 16, k byte-halves)
    const uint32_t b_row  = (uint32_t)((lane & 7) + ((lane >> 4) & 1) * 8);
    const uint32_t b_coff = (uint32_t)(((lane >> 3) & 1) * 16);
    uint32_t Bf[2][4][4];               // [nt(16-col pair)][ks][4 regs = two n8 tiles]
    #pragma unroll
    for (int nt = 0; nt < 2; nt++)
        #pragma unroll
        for (int ks = 0; ks < 4; ks++)
            ldmx4(Bf[nt][ks],
                  sbase + OFF_W + (uint32_t)(ch * 32 + nt * 16 + b_row) * 144 + b_coff + ks * 32);

    // A-tile lane addresses
    const uint32_t a_row  = (uint32_t)((lane & 7) + ((lane >> 3) & 1) * 8);
    const uint32_t a_coff = (uint32_t)(((lane >> 4) & 1) * 16);

    const float4* w1a = (const float4*)(sW11 + half * 32);
    const float4* w1b = (const float4*)(sW12 + half * 32);

    // h1 builder: gather + coords + gelu -> fp16 tile (pitch 144)
    auto build_h1 = [&](int s, uint32_t aoff) {
        int idx = sidx[s * 128 + r];
        const float4* Ap = (const float4*)(g_A + sab[r] + idx * 64 + half * 32);
        float px = spx[r], py = spy[r];
        uint32_t hp[16];
        #pragma unroll
        for (int q = 0; q < 8; q++) {
            float4 a  = Ap[q];
            float4 wa = w1a[q];
            float4 wb = w1b[q];
            float g0 = geluf(fmaf(wa.x, px, fmaf(wb.x, py, a.x)));
            float g1 = geluf(fmaf(wa.y, px, fmaf(wb.y, py, a.y)));
            float g2 = geluf(fmaf(wa.z, px, fmaf(wb.z, py, a.z)));
            float g3 = geluf(fmaf(wa.w, px, fmaf(wb.w, py, a.w)));
            hp[q * 2 + 0] = packh2(g0, g1);
            hp[q * 2 + 1] = packh2(g2, g3);
        }
        char* row = smem + aoff + r * 144 + half * 64;
        #pragma unroll
        for (int t = 0; t < 4; t++)
            *(uint4*)(row + t * 16) = make_uint4(hp[4*t], hp[4*t+1], hp[4*t+2], hp[4*t+3]);
    };

    float h2acc[2][4][4];
    #pragma unroll
    for (int mt = 0; mt < 2; mt++)
        #pragma unroll
        for (int nt = 0; nt < 4; nt++)
            #pragma unroll
            for (int i = 0; i < 4; i++) h2acc[mt][nt][i] = 0.0f;

    build_h1(0, OFF_A0);
    __syncthreads();

    for (int s = 0; s < NSAMP; s++) {
        const uint32_t abase = sbase + (s & 1 ? OFF_A1 : OFF_A0);

        // ---- MMA: warp (rg,ch) computes rows 32rg..+31 x cols 32ch..+31 ----
        float c[2][4][4];
        #pragma unroll
        for (int mt = 0; mt < 2; mt++)
            #pragma unroll
            for (int nt = 0; nt < 4; nt++)
                #pragma unroll
                for (int i = 0; i < 4; i++) c[mt][nt][i] = 0.0f;

        #pragma unroll
        for (int mt = 0; mt < 2; mt++) {
            uint32_t arow = abase + (uint32_t)(rg * 32 + mt * 16 + a_row) * 144 + a_coff;
            #pragma unroll
            for (int ks = 0; ks < 4; ks++) {
                uint32_t af[4];
                ldmx4(af, arow + ks * 32);
                #pragma unroll
                for (int nt = 0; nt < 2; nt++) {
                    mma16816(c[mt][nt * 2 + 0], af, Bf[nt][ks][0], Bf[nt][ks][1]);
                    mma16816(c[mt][nt * 2 + 1], af, Bf[nt][ks][2], Bf[nt][ks][3]);
                }
            }
        }
        // epilogue: bias + gelu + accumulate (register-only)
        {
            int jq = ch * 32 + (lane & 3) * 2;
            #pragma unroll
            for (int nti = 0; nti < 4; nti++) {
                float bj0 = sb2[jq + nti * 8], bj1 = sb2[jq + nti * 8 + 1];
                #pragma unroll
                for (int mt = 0; mt < 2; mt++) {
                    h2acc[mt][nti][0] += geluf(c[mt][nti][0] + bj0);
                    h2acc[mt][nti][1] += geluf(c[mt][nti][1] + bj1);
                    h2acc[mt][nti][2] += geluf(c[mt][nti][2] + bj0);
                    h2acc[mt][nti][3] += geluf(c[mt][nti][3] + bj1);
                }
            }
        }

        if (s + 1 < NSAMP) build_h1(s + 1, (s + 1) & 1 ? OFF_A1 : OFF_A0);
        __syncthreads();   // build(s+1) visible; all warps done MMA(s)
    }

    // ---- h2 mean -> smem [128][72] (reuses A region) ----
    float* h2m = (float*)(smem + OFF_A0);
    {
        const float inv = 1.0f / 12.0f;
        int r0 = rg * 32 + (lane >> 2);
        int c0 = ch * 32 + (lane & 3) * 2;
        #pragma unroll
        for (int mt = 0; mt < 2; mt++)
            #pragma unroll
            for (int nti = 0; nti < 4; nti++) {
                int row = r0 + mt * 16;
                int col = c0 + nti * 8;
                h2m[row * 72 + col]           = h2acc[mt][nti][0] * inv;
                h2m[row * 72 + col + 1]       = h2acc[mt][nti][1] * inv;
                h2m[(row + 8) * 72 + col]     = h2acc[mt][nti][2] * inv;
                h2m[(row + 8) * 72 + col + 1] = h2acc[mt][nti][3] * inv;
            }
    }
    __syncthreads();

    // ---- layer 3 (mean folded): thread (r, half) covers j in [32*half, 32*half+32) ----
    {
        float pacc[COUT];
        #pragma unroll
        for (int c = 0; c < COUT; c++) pacc[c] = 0.0f;
        const float* hrow = h2m + r * 72 + half * 32;
        #pragma unroll
        for (int q = 0; q < 8; q++) {
            float4 h4 = *(const float4*)(hrow + q * 4);
            int j = half * 32 + q * 4;
            #pragma unroll
            for (int c = 0; c < COUT; c++) {
                const float* w3r = sW3 + c * HID + j;
                pacc[c] = fmaf(w3r[0], h4.x, pacc[c]);
                pacc[c] = fmaf(w3r[1], h4.y, pacc[c]);
                pacc[c] = fmaf(w3r[2], h4.z, pacc[c]);
                pacc[c] = fmaf(w3r[3], h4.w, pacc[c]);
            }
        }
        if (half == 1) {
            #pragma unroll
            for (int c = 0; c < COUT; c++) part[r * COUT + c] = pacc[c];
        }
        __syncthreads();
        if (half == 0) {
            size_t base = (size_t)b * COUT * NPIX + n0 + r;
            #pragma unroll
            for (int c = 0; c < COUT; c++)
                out[base + (size_t)c * NPIX] = pacc[c] + part[r * COUT + c] + __ldg(b3 + c);
        }
    }
}

// ---------------- launch ----------------
extern "C" void kernel_launch(void* const* d_in, const int* in_sizes, int n_in,
                              void* d_out, int out_size) {
    const float* ref    = (const float*)d_in[0];
    const float* pc     = (const float*)d_in[1];
    const int*   lookup = (const int*)d_in[2];
    const int*   samp   = (const int*)d_in[3];
    const float* W1     = (const float*)d_in[4];
    const float* b1     = (const float*)d_in[5];
    const float* W2     = (const float*)d_in[6];
    const float* b2     = (const float*)d_in[7];
    const float* W3     = (const float*)d_in[8];
    const float* b3     = (const float*)d_in[9];
    float* out = (float*)d_out;

    cudaFuncSetAttribute(mlp_mma_kernel, cudaFuncAttributeMaxDynamicSharedMemorySize, SMEM_TOTAL);

    precompute_A<<<NB * NS, 256>>>(ref, W1, b1);
    mlp_mma_kernel<<<NB * (NPIX / 128), 256, SMEM_TOTAL>>>(
        pc, lookup, samp, W1, W2, b2, W3, b3, out);
}